// round 3
// baseline (speedup 1.0000x reference)
#include <cuda_runtime.h>

#define T_ 8
#define K_ 4
#define B_ 8

// Per-voxel time-expanded lattices: lat[v] = 8 x float4, channel = t*4+k
__device__ float4 g_lat0[512 * 8];      //  8^3
__device__ float4 g_lat1[4096 * 8];     // 16^3
__device__ float4 g_lat2[32768 * 8];    // 32^3
__device__ float  g_basis[T_ * B_];

__constant__ float c_knots[12] = {0.f,0.f,0.f,0.f,1.f,2.f,4.f,8.f,16.f,16.f,16.f,16.f};

// ---------------------------------------------------------------------------
// Kernel 1: Cox-de Boor basis, one thread per time sample (T=8)
// ---------------------------------------------------------------------------
__global__ void basis_kernel(const float* __restrict__ t_in) {
    int ti = threadIdx.x;
    if (ti >= T_) return;
    float t = t_in[ti];
    float N[11];
    #pragma unroll
    for (int i = 0; i < 11; i++) {
        float l = c_knots[i], r = c_knots[i + 1];
        bool m = (i < 10) ? (t >= l && t < r) : (t >= l && t <= r);
        N[i] = m ? 1.f : 0.f;
    }
    #pragma unroll
    for (int p = 1; p <= 3; p++) {
        float Nn[11];
        for (int i = 0; i < 11 - p; i++) {
            float l = c_knots[i], mid = c_knots[i + p];
            float rr = c_knots[i + 1], fr = c_knots[i + p + 1];
            float term = 0.f;
            if (mid > l)  term += (t - l) / (mid - l) * N[i];
            if (fr > rr)  term += (fr - t) / (fr - rr) * N[i + 1];
            Nn[i] = term;
        }
        for (int i = 0; i < 11 - p; i++) N[i] = Nn[i];
    }
    #pragma unroll
    for (int b = 0; b < B_; b++) g_basis[ti * B_ + b] = N[b];
}

// ---------------------------------------------------------------------------
// Kernel 2: per-voxel lat[v][t][k] = static[k,v] + sum_b basis[t,b]*coef[k,v,b]
// ---------------------------------------------------------------------------
__global__ void precompute_kernel(const float* __restrict__ stat,
                                  const float* __restrict__ coef,
                                  int Nvox, int which) {
    int v = blockIdx.x * blockDim.x + threadIdx.x;
    if (v >= Nvox) return;
    float4* lat = (which == 0) ? g_lat0 : (which == 1) ? g_lat1 : g_lat2;

    float bas[T_ * B_];
    #pragma unroll
    for (int i = 0; i < T_ * B_; i++) bas[i] = g_basis[i];

    float st[K_];
    #pragma unroll
    for (int k = 0; k < K_; k++) st[k] = stat[k * Nvox + v];

    float cf[K_][B_];
    #pragma unroll
    for (int k = 0; k < K_; k++) {
        const float4* cp = reinterpret_cast<const float4*>(coef + ((size_t)(k * Nvox) + v) * B_);
        float4 c0 = cp[0], c1 = cp[1];
        cf[k][0] = c0.x; cf[k][1] = c0.y; cf[k][2] = c0.z; cf[k][3] = c0.w;
        cf[k][4] = c1.x; cf[k][5] = c1.y; cf[k][6] = c1.z; cf[k][7] = c1.w;
    }

    #pragma unroll
    for (int t = 0; t < T_; t++) {
        float o[K_];
        #pragma unroll
        for (int k = 0; k < K_; k++) {
            float s = st[k];
            #pragma unroll
            for (int b = 0; b < B_; b++) s = fmaf(bas[t * B_ + b], cf[k][b], s);
            o[k] = s;
        }
        lat[(size_t)v * 8 + t] = make_float4(o[0], o[1], o[2], o[3]);
    }
}

// ---------------------------------------------------------------------------
// Kernel 3: per-point tricubic gather-accumulate over 3 lattices
// ---------------------------------------------------------------------------
__device__ __forceinline__ void cubw(float u, float w[4]) {
    float u2 = u * u, u3 = u2 * u;
    w[0] = (1.f / 6.f) * (1.f - 3.f * u + 3.f * u2 - u3);
    w[1] = (1.f / 6.f) * (4.f - 6.f * u2 + 3.f * u3);
    w[2] = (1.f / 6.f) * (1.f + 3.f * u + 3.f * u2 - 3.f * u3);
    w[3] = (1.f / 6.f) * u3;
}

__device__ __forceinline__ unsigned long long pack2(float w) {
    unsigned long long r;
    unsigned int wi = __float_as_uint(w);
    asm("mov.b64 %0, {%1, %1};" : "=l"(r) : "r"(wi));
    return r;
}

__device__ __forceinline__ void ffma2(unsigned long long& d,
                                      unsigned long long a,
                                      unsigned long long b) {
    asm("fma.rn.f32x2 %0, %1, %2, %0;" : "+l"(d) : "l"(a), "l"(b));
}

__device__ __forceinline__ void accum_lattice(const float4* __restrict__ lat, int n,
                                              float scale, float px, float py, float pz,
                                              unsigned long long acc[16]) {
    float cx = px * scale, cy = py * scale, cz = pz * scale;
    float fx = floorf(cx), fy = floorf(cy), fz = floorf(cz);
    int ix = (int)fx - 1, iy = (int)fy - 1, iz = (int)fz - 1;
    float wx[4], wy[4], wz[4];
    cubw(cx - fx, wx); cubw(cy - fy, wy); cubw(cz - fz, wz);
    int X[4], Y[4], Z[4];
    #pragma unroll
    for (int a = 0; a < 4; a++) {
        X[a] = min(max(ix + a, 0), n - 1);
        Y[a] = min(max(iy + a, 0), n - 1);
        Z[a] = min(max(iz + a, 0), n - 1);
    }
    #pragma unroll
    for (int a = 0; a < 4; a++) {
        int xb = X[a] * n;
        #pragma unroll
        for (int b = 0; b < 4; b++) {
            float wab = wx[a] * wy[b];
            const ulonglong2* rowp =
                reinterpret_cast<const ulonglong2*>(lat + (size_t)((xb + Y[b]) * n) * 8);
            #pragma unroll
            for (int c = 0; c < 4; c++) {
                unsigned long long w2 = pack2(wab * wz[c]);
                const ulonglong2* vp = rowp + (size_t)Z[c] * 8;
                #pragma unroll
                for (int q = 0; q < 8; q++) {
                    ulonglong2 v = vp[q];
                    ffma2(acc[2 * q],     v.x, w2);
                    ffma2(acc[2 * q + 1], v.y, w2);
                }
            }
        }
    }
}

__global__ void __launch_bounds__(256)
main_kernel(const float* __restrict__ coords, ulonglong2* __restrict__ out, int P) {
    int p = blockIdx.x * blockDim.x + threadIdx.x;
    if (p >= P) return;
    float px = coords[3 * p], py = coords[3 * p + 1], pz = coords[3 * p + 2];

    unsigned long long acc[16];
    #pragma unroll
    for (int i = 0; i < 16; i++) acc[i] = 0ULL;   // packed (0.f, 0.f)

    accum_lattice(g_lat0,  8,  7.f / 31.f, px, py, pz, acc);
    accum_lattice(g_lat1, 16, 15.f / 31.f, px, py, pz, acc);
    accum_lattice(g_lat2, 32, 31.f / 31.f, px, py, pz, acc);

    // out is (T, P, K) fp32; per (t,p) a 16B store of the 4 classes
    #pragma unroll
    for (int t = 0; t < T_; t++) {
        ulonglong2 o;
        o.x = acc[2 * t];
        o.y = acc[2 * t + 1];
        out[(size_t)t * P + p] = o;
    }
}

// ---------------------------------------------------------------------------
extern "C" void kernel_launch(void* const* d_in, const int* in_sizes, int n_in,
                              void* d_out, int out_size) {
    // metadata order (dict insertion order of setup_inputs):
    //   0: t, 1: coords, 2: static_0, 3: coeffs_0, 4: static_1, 5: coeffs_1,
    //   6: static_2, 7: coeffs_2   (static_i and coeffs_i are INTERLEAVED)
    const float* t_in   = (const float*)d_in[0];
    const float* coords = (const float*)d_in[1];
    const float* st0 = (const float*)d_in[2];
    const float* cf0 = (const float*)d_in[3];
    const float* st1 = (const float*)d_in[4];
    const float* cf1 = (const float*)d_in[5];
    const float* st2 = (const float*)d_in[6];
    const float* cf2 = (const float*)d_in[7];
    int P = in_sizes[1] / 3;

    basis_kernel<<<1, 32>>>(t_in);

    precompute_kernel<<<(512   + 127) / 128, 128>>>(st0, cf0, 512,   0);
    precompute_kernel<<<(4096  + 127) / 128, 128>>>(st1, cf1, 4096,  1);
    precompute_kernel<<<(32768 + 127) / 128, 128>>>(st2, cf2, 32768, 2);

    main_kernel<<<(P + 255) / 256, 256>>>(coords, (ulonglong2*)d_out, P);
}

// round 4
// speedup vs baseline: 4.6361x; 4.6361x over previous
#include <cuda_runtime.h>

#define T_ 8
#define K_ 4
#define B_ 8

// Per-voxel time-expanded lattices: lat[v] = 8 x float4, channel index = t (float4 = 4 classes)
__device__ float4 g_lat0[512 * 8];      //  8^3
__device__ float4 g_lat1[4096 * 8];     // 16^3
__device__ float4 g_lat2[32768 * 8];    // 32^3
__device__ float  g_basis[T_ * B_];

__constant__ float c_knots[12] = {0.f,0.f,0.f,0.f,1.f,2.f,4.f,8.f,16.f,16.f,16.f,16.f};

// ---------------------------------------------------------------------------
// Kernel 1: Cox-de Boor basis, one thread per time sample (T=8)
// ---------------------------------------------------------------------------
__global__ void basis_kernel(const float* __restrict__ t_in) {
    int ti = threadIdx.x;
    if (ti >= T_) return;
    float t = t_in[ti];
    float N[11];
    #pragma unroll
    for (int i = 0; i < 11; i++) {
        float l = c_knots[i], r = c_knots[i + 1];
        bool m = (i < 10) ? (t >= l && t < r) : (t >= l && t <= r);
        N[i] = m ? 1.f : 0.f;
    }
    #pragma unroll
    for (int p = 1; p <= 3; p++) {
        float Nn[11];
        for (int i = 0; i < 11 - p; i++) {
            float l = c_knots[i], mid = c_knots[i + p];
            float rr = c_knots[i + 1], fr = c_knots[i + p + 1];
            float term = 0.f;
            if (mid > l)  term += (t - l) / (mid - l) * N[i];
            if (fr > rr)  term += (fr - t) / (fr - rr) * N[i + 1];
            Nn[i] = term;
        }
        for (int i = 0; i < 11 - p; i++) N[i] = Nn[i];
    }
    #pragma unroll
    for (int b = 0; b < B_; b++) g_basis[ti * B_ + b] = N[b];
}

// ---------------------------------------------------------------------------
// Kernel 2: per-voxel lat[v][t][k] = static[k,v] + sum_b basis[t,b]*coef[k,v,b]
// ---------------------------------------------------------------------------
__global__ void precompute_kernel(const float* __restrict__ stat,
                                  const float* __restrict__ coef,
                                  int Nvox, int which) {
    int v = blockIdx.x * blockDim.x + threadIdx.x;
    if (v >= Nvox) return;
    float4* lat = (which == 0) ? g_lat0 : (which == 1) ? g_lat1 : g_lat2;

    float bas[T_ * B_];
    #pragma unroll
    for (int i = 0; i < T_ * B_; i++) bas[i] = g_basis[i];

    float st[K_];
    #pragma unroll
    for (int k = 0; k < K_; k++) st[k] = stat[k * Nvox + v];

    float cf[K_][B_];
    #pragma unroll
    for (int k = 0; k < K_; k++) {
        const float4* cp = reinterpret_cast<const float4*>(coef + ((size_t)(k * Nvox) + v) * B_);
        float4 c0 = cp[0], c1 = cp[1];
        cf[k][0] = c0.x; cf[k][1] = c0.y; cf[k][2] = c0.z; cf[k][3] = c0.w;
        cf[k][4] = c1.x; cf[k][5] = c1.y; cf[k][6] = c1.z; cf[k][7] = c1.w;
    }

    #pragma unroll
    for (int t = 0; t < T_; t++) {
        float o[K_];
        #pragma unroll
        for (int k = 0; k < K_; k++) {
            float s = st[k];
            #pragma unroll
            for (int b = 0; b < B_; b++) s = fmaf(bas[t * B_ + b], cf[k][b], s);
            o[k] = s;
        }
        lat[(size_t)v * 8 + t] = make_float4(o[0], o[1], o[2], o[3]);
    }
}

// ---------------------------------------------------------------------------
// Kernel 3: cooperative tricubic gather. 8 lanes per point; lane tl owns time
// slot tl (one float4 = 4 classes). Each 128B voxel line is fetched by 8
// coalesced LDG.128s -> 4 wavefronts per warp-load instead of 32.
// ---------------------------------------------------------------------------
__device__ __forceinline__ void cubw(float u, float w[4]) {
    float u2 = u * u, u3 = u2 * u;
    w[0] = (1.f / 6.f) * (1.f - 3.f * u + 3.f * u2 - u3);
    w[1] = (1.f / 6.f) * (4.f - 6.f * u2 + 3.f * u3);
    w[2] = (1.f / 6.f) * (1.f + 3.f * u + 3.f * u2 - 3.f * u3);
    w[3] = (1.f / 6.f) * u3;
}

__device__ __forceinline__ unsigned long long pack2(float w) {
    unsigned long long r;
    unsigned int wi = __float_as_uint(w);
    asm("mov.b64 %0, {%1, %1};" : "=l"(r) : "r"(wi));
    return r;
}

__device__ __forceinline__ void ffma2(unsigned long long& d,
                                      unsigned long long a,
                                      unsigned long long b) {
    asm("fma.rn.f32x2 %0, %1, %2, %0;" : "+l"(d) : "l"(a), "l"(b));
}

__device__ __forceinline__ void accum_lattice_coop(const float4* __restrict__ lat, int n,
                                                   float scale, float px, float py, float pz,
                                                   int tl, unsigned long long acc[2]) {
    float cx = px * scale, cy = py * scale, cz = pz * scale;
    float fx = floorf(cx), fy = floorf(cy), fz = floorf(cz);
    int ix = (int)fx - 1, iy = (int)fy - 1, iz = (int)fz - 1;
    float wx[4], wy[4], wz[4];
    cubw(cx - fx, wx); cubw(cy - fy, wy); cubw(cz - fz, wz);
    int X[4], Y[4];
    int zoff[4];
    #pragma unroll
    for (int a = 0; a < 4; a++) {
        X[a] = min(max(ix + a, 0), n - 1);
        Y[a] = min(max(iy + a, 0), n - 1);
        zoff[a] = min(max(iz + a, 0), n - 1) * 8;   // float4 units
    }
    #pragma unroll
    for (int a = 0; a < 4; a++) {
        int xb = X[a] * n;
        #pragma unroll
        for (int b = 0; b < 4; b++) {
            float wab = wx[a] * wy[b];
            // row base for this (x,y): voxel line + this lane's 16B slice
            const ulonglong2* rowp =
                reinterpret_cast<const ulonglong2*>(lat + ((size_t)(xb + Y[b]) * n) * 8 + tl);
            #pragma unroll
            for (int c = 0; c < 4; c++) {
                unsigned long long w2 = pack2(wab * wz[c]);
                ulonglong2 v = rowp[zoff[c]];        // ulonglong2 == float4 slice at slot tl
                ffma2(acc[0], v.x, w2);
                ffma2(acc[1], v.y, w2);
            }
        }
    }
}

__global__ void __launch_bounds__(256)
main_kernel(const float* __restrict__ coords, ulonglong2* __restrict__ out, int P) {
    int warp = blockIdx.x * (blockDim.x >> 5) + (threadIdx.x >> 5);
    int lane = threadIdx.x & 31;
    int sub  = lane >> 3;     // point slot within warp (0..3)
    int tl   = lane & 7;      // time slot (0..7)
    int p = warp * 4 + sub;
    if (p >= P) return;

    float px = coords[3 * p], py = coords[3 * p + 1], pz = coords[3 * p + 2];

    unsigned long long acc[2] = {0ULL, 0ULL};   // packed (k0,k1),(k2,k3) for time tl

    accum_lattice_coop(g_lat0,  8,  7.f / 31.f, px, py, pz, tl, acc);
    accum_lattice_coop(g_lat1, 16, 15.f / 31.f, px, py, pz, tl, acc);
    accum_lattice_coop(g_lat2, 32, 31.f / 31.f, px, py, pz, tl, acc);

    // out is (T, P, K) fp32; this lane owns (t=tl, p): one 16B store
    ulonglong2 o; o.x = acc[0]; o.y = acc[1];
    out[(size_t)tl * P + p] = o;
}

// ---------------------------------------------------------------------------
extern "C" void kernel_launch(void* const* d_in, const int* in_sizes, int n_in,
                              void* d_out, int out_size) {
    // metadata order: 0:t 1:coords 2:static_0 3:coeffs_0 4:static_1 5:coeffs_1
    //                 6:static_2 7:coeffs_2  (static/coeffs INTERLEAVED)
    const float* t_in   = (const float*)d_in[0];
    const float* coords = (const float*)d_in[1];
    const float* st0 = (const float*)d_in[2];
    const float* cf0 = (const float*)d_in[3];
    const float* st1 = (const float*)d_in[4];
    const float* cf1 = (const float*)d_in[5];
    const float* st2 = (const float*)d_in[6];
    const float* cf2 = (const float*)d_in[7];
    int P = in_sizes[1] / 3;

    basis_kernel<<<1, 32>>>(t_in);

    precompute_kernel<<<(512   + 127) / 128, 128>>>(st0, cf0, 512,   0);
    precompute_kernel<<<(4096  + 127) / 128, 128>>>(st1, cf1, 4096,  1);
    precompute_kernel<<<(32768 + 127) / 128, 128>>>(st2, cf2, 32768, 2);

    // 8 lanes per point -> 4 points per warp -> 32 points per 256-thread block
    int nblocks = (P + 31) / 32;
    main_kernel<<<nblocks, 256>>>(coords, (ulonglong2*)d_out, P);
}

// round 5
// speedup vs baseline: 4.9367x; 1.0648x over previous
#include <cuda_runtime.h>

#define T_ 8
#define K_ 4
#define B_ 8
#define MAXP 262144
#define NCELL 31
#define NB (NCELL * NCELL * NCELL)   // 29791 fine-cell bins

// Per-voxel time-expanded lattices: lat[v] = 8 x float4 (t-major, float4 = 4 classes)
__device__ float4 g_lat0[512 * 8];      //  8^3
__device__ float4 g_lat1[4096 * 8];     // 16^3
__device__ float4 g_lat2[32768 * 8];    // 32^3
__device__ float  g_basis[T_ * B_];

// Counting-sort scratch
__device__ float4 g_sorted[MAXP];       // (x, y, z, orig_idx bits)
__device__ int    g_hist[NB];
__device__ int    g_base[NB];
__device__ int    g_cur[NB];

__constant__ float c_knots[12] = {0.f,0.f,0.f,0.f,1.f,2.f,4.f,8.f,16.f,16.f,16.f,16.f};

// ---------------------------------------------------------------------------
// Kernel 1: Cox-de Boor basis, one thread per time sample (T=8)
// ---------------------------------------------------------------------------
__global__ void basis_kernel(const float* __restrict__ t_in) {
    int ti = threadIdx.x;
    if (ti >= T_) return;
    float t = t_in[ti];
    float N[11];
    #pragma unroll
    for (int i = 0; i < 11; i++) {
        float l = c_knots[i], r = c_knots[i + 1];
        bool m = (i < 10) ? (t >= l && t < r) : (t >= l && t <= r);
        N[i] = m ? 1.f : 0.f;
    }
    #pragma unroll
    for (int p = 1; p <= 3; p++) {
        float Nn[11];
        for (int i = 0; i < 11 - p; i++) {
            float l = c_knots[i], mid = c_knots[i + p];
            float rr = c_knots[i + 1], fr = c_knots[i + p + 1];
            float term = 0.f;
            if (mid > l)  term += (t - l) / (mid - l) * N[i];
            if (fr > rr)  term += (fr - t) / (fr - rr) * N[i + 1];
            Nn[i] = term;
        }
        for (int i = 0; i < 11 - p; i++) N[i] = Nn[i];
    }
    #pragma unroll
    for (int b = 0; b < B_; b++) g_basis[ti * B_ + b] = N[b];
}

// ---------------------------------------------------------------------------
// Kernel 2: per-voxel lat[v][t][k] = static[k,v] + sum_b basis[t,b]*coef[k,v,b]
// ---------------------------------------------------------------------------
__global__ void precompute_kernel(const float* __restrict__ stat,
                                  const float* __restrict__ coef,
                                  int Nvox, int which) {
    int v = blockIdx.x * blockDim.x + threadIdx.x;
    if (v >= Nvox) return;
    float4* lat = (which == 0) ? g_lat0 : (which == 1) ? g_lat1 : g_lat2;

    float bas[T_ * B_];
    #pragma unroll
    for (int i = 0; i < T_ * B_; i++) bas[i] = g_basis[i];

    float st[K_];
    #pragma unroll
    for (int k = 0; k < K_; k++) st[k] = stat[k * Nvox + v];

    float cf[K_][B_];
    #pragma unroll
    for (int k = 0; k < K_; k++) {
        const float4* cp = reinterpret_cast<const float4*>(coef + ((size_t)(k * Nvox) + v) * B_);
        float4 c0 = cp[0], c1 = cp[1];
        cf[k][0] = c0.x; cf[k][1] = c0.y; cf[k][2] = c0.z; cf[k][3] = c0.w;
        cf[k][4] = c1.x; cf[k][5] = c1.y; cf[k][6] = c1.z; cf[k][7] = c1.w;
    }

    #pragma unroll
    for (int t = 0; t < T_; t++) {
        float o[K_];
        #pragma unroll
        for (int k = 0; k < K_; k++) {
            float s = st[k];
            #pragma unroll
            for (int b = 0; b < B_; b++) s = fmaf(bas[t * B_ + b], cf[k][b], s);
            o[k] = s;
        }
        lat[(size_t)v * 8 + t] = make_float4(o[0], o[1], o[2], o[3]);
    }
}

// ---------------------------------------------------------------------------
// Counting sort by fine-lattice cell id
// ---------------------------------------------------------------------------
__device__ __forceinline__ int cell_of(float px, float py, float pz) {
    int fx = min(max((int)floorf(px), 0), NCELL - 1);
    int fy = min(max((int)floorf(py), 0), NCELL - 1);
    int fz = min(max((int)floorf(pz), 0), NCELL - 1);
    return (fx * NCELL + fy) * NCELL + fz;
}

__global__ void zero_kernel() {
    int i = blockIdx.x * blockDim.x + threadIdx.x;
    if (i < NB) { g_hist[i] = 0; g_cur[i] = 0; }
}

__global__ void hist_kernel(const float* __restrict__ coords, int P) {
    int p = blockIdx.x * blockDim.x + threadIdx.x;
    if (p >= P) return;
    atomicAdd(&g_hist[cell_of(coords[3*p], coords[3*p+1], coords[3*p+2])], 1);
}

__global__ void scan_kernel() {
    __shared__ int part[1024];
    int tid = threadIdx.x;
    const int CH = (NB + 1023) / 1024;        // 30
    int start = tid * CH, end = min(start + CH, NB);
    int s = 0;
    for (int i = start; i < end; i++) s += g_hist[i];
    part[tid] = s;
    __syncthreads();
    // Hillis-Steele inclusive scan over 1024 partials
    for (int off = 1; off < 1024; off <<= 1) {
        int v = (tid >= off) ? part[tid - off] : 0;
        __syncthreads();
        part[tid] += v;
        __syncthreads();
    }
    int run = part[tid] - s;                  // exclusive prefix
    for (int i = start; i < end; i++) { g_base[i] = run; run += g_hist[i]; }
}

__global__ void scatter_kernel(const float* __restrict__ coords, int P) {
    int p = blockIdx.x * blockDim.x + threadIdx.x;
    if (p >= P) return;
    float px = coords[3*p], py = coords[3*p+1], pz = coords[3*p+2];
    int bin = cell_of(px, py, pz);
    int pos = g_base[bin] + atomicAdd(&g_cur[bin], 1);
    g_sorted[pos] = make_float4(px, py, pz, __int_as_float(p));
}

// ---------------------------------------------------------------------------
// Kernel 3: cooperative tricubic gather over sorted points.
// 8 lanes per point (lane tl owns time slot tl); 4 points per warp, and after
// the sort those 4 points almost always share the fine cell -> all 32 lanes
// of a tap load hit the SAME 128B voxel line (1 wavefront, L1-resident).
// ---------------------------------------------------------------------------
__device__ __forceinline__ void cubw(float u, float w[4]) {
    float u2 = u * u, u3 = u2 * u;
    w[0] = (1.f / 6.f) * (1.f - 3.f * u + 3.f * u2 - u3);
    w[1] = (1.f / 6.f) * (4.f - 6.f * u2 + 3.f * u3);
    w[2] = (1.f / 6.f) * (1.f + 3.f * u + 3.f * u2 - 3.f * u3);
    w[3] = (1.f / 6.f) * u3;
}

__device__ __forceinline__ unsigned long long pack2(float w) {
    unsigned long long r;
    unsigned int wi = __float_as_uint(w);
    asm("mov.b64 %0, {%1, %1};" : "=l"(r) : "r"(wi));
    return r;
}

__device__ __forceinline__ void ffma2(unsigned long long& d,
                                      unsigned long long a,
                                      unsigned long long b) {
    asm("fma.rn.f32x2 %0, %1, %2, %0;" : "+l"(d) : "l"(a), "l"(b));
}

__device__ __forceinline__ void accum_lattice_coop(const float4* __restrict__ lat, int n,
                                                   float scale, float px, float py, float pz,
                                                   int tl, unsigned long long acc[2]) {
    float cx = px * scale, cy = py * scale, cz = pz * scale;
    float fx = floorf(cx), fy = floorf(cy), fz = floorf(cz);
    int ix = (int)fx - 1, iy = (int)fy - 1, iz = (int)fz - 1;
    float wx[4], wy[4], wz[4];
    cubw(cx - fx, wx); cubw(cy - fy, wy); cubw(cz - fz, wz);
    int X[4], Y[4];
    int zoff[4];
    #pragma unroll
    for (int a = 0; a < 4; a++) {
        X[a] = min(max(ix + a, 0), n - 1);
        Y[a] = min(max(iy + a, 0), n - 1);
        zoff[a] = min(max(iz + a, 0), n - 1) * 8;   // float4 units
    }
    #pragma unroll
    for (int a = 0; a < 4; a++) {
        int xb = X[a] * n;
        #pragma unroll
        for (int b = 0; b < 4; b++) {
            float wab = wx[a] * wy[b];
            const ulonglong2* rowp =
                reinterpret_cast<const ulonglong2*>(lat + ((size_t)(xb + Y[b]) * n) * 8 + tl);
            #pragma unroll
            for (int c = 0; c < 4; c++) {
                unsigned long long w2 = pack2(wab * wz[c]);
                ulonglong2 v = rowp[zoff[c]];
                ffma2(acc[0], v.x, w2);
                ffma2(acc[1], v.y, w2);
            }
        }
    }
}

__global__ void __launch_bounds__(256)
main_kernel(ulonglong2* __restrict__ out, int P) {
    int warp = blockIdx.x * (blockDim.x >> 5) + (threadIdx.x >> 5);
    int lane = threadIdx.x & 31;
    int sub  = lane >> 3;     // point slot within warp (0..3)
    int tl   = lane & 7;      // time slot (0..7)
    int p = warp * 4 + sub;
    if (p >= P) return;

    float4 s = g_sorted[p];
    float px = s.x, py = s.y, pz = s.z;
    int orig = __float_as_int(s.w);

    unsigned long long acc[2] = {0ULL, 0ULL};   // packed (k0,k1),(k2,k3) at time tl

    accum_lattice_coop(g_lat0,  8,  7.f / 31.f, px, py, pz, tl, acc);
    accum_lattice_coop(g_lat1, 16, 15.f / 31.f, px, py, pz, tl, acc);
    accum_lattice_coop(g_lat2, 32, 31.f / 31.f, px, py, pz, tl, acc);

    // out is (T, P, K) fp32; this lane owns (t=tl, orig): one 16B store
    ulonglong2 o; o.x = acc[0]; o.y = acc[1];
    out[(size_t)tl * P + orig] = o;
}

// ---------------------------------------------------------------------------
extern "C" void kernel_launch(void* const* d_in, const int* in_sizes, int n_in,
                              void* d_out, int out_size) {
    // metadata order: 0:t 1:coords 2:static_0 3:coeffs_0 4:static_1 5:coeffs_1
    //                 6:static_2 7:coeffs_2  (static/coeffs INTERLEAVED)
    const float* t_in   = (const float*)d_in[0];
    const float* coords = (const float*)d_in[1];
    const float* st0 = (const float*)d_in[2];
    const float* cf0 = (const float*)d_in[3];
    const float* st1 = (const float*)d_in[4];
    const float* cf1 = (const float*)d_in[5];
    const float* st2 = (const float*)d_in[6];
    const float* cf2 = (const float*)d_in[7];
    int P = in_sizes[1] / 3;
    if (P > MAXP) P = MAXP;

    basis_kernel<<<1, 32>>>(t_in);

    precompute_kernel<<<(512   + 127) / 128, 128>>>(st0, cf0, 512,   0);
    precompute_kernel<<<(4096  + 127) / 128, 128>>>(st1, cf1, 4096,  1);
    precompute_kernel<<<(32768 + 127) / 128, 128>>>(st2, cf2, 32768, 2);

    // counting sort by fine cell
    zero_kernel<<<(NB + 255) / 256, 256>>>();
    hist_kernel<<<(P + 255) / 256, 256>>>(coords, P);
    scan_kernel<<<1, 1024>>>();
    scatter_kernel<<<(P + 255) / 256, 256>>>(coords, P);

    // 8 lanes per point -> 4 points per warp -> 32 points per 256-thread block
    int nblocks = (P + 31) / 32;
    main_kernel<<<nblocks, 256>>>((ulonglong2*)d_out, P);
}

// round 6
// speedup vs baseline: 5.0338x; 1.0197x over previous
#include <cuda_runtime.h>

#define T_ 8
#define K_ 4
#define B_ 8
#define MAXP 262144
#define NCELL 31
#define NB (NCELL * NCELL * NCELL)   // 29791 bins
#define CAP 16
#define SPILLCAP 32768
#define BIN_BLOCKS ((NB + 7) / 8)    // 3724 (8 warps/block, warp per bin)
#define SPILL_BLOCKS 64
#define SPILL_STRIDE (SPILL_BLOCKS * 8 * 4)

// Per-voxel time-expanded lattices: lat[v] = 8 x float4 (t-major; float4 = 4 classes)
__device__ float4 g_lat0[512 * 8];
__device__ float4 g_lat1[4096 * 8];
__device__ float4 g_lat2[32768 * 8];
__device__ float  g_basis[T_ * B_];

// Scan-free binning
__device__ float4 g_bucket[NB * CAP];   // (x,y,z, orig idx bits)
__device__ int    g_cnt[NB];
__device__ float4 g_spill[SPILLCAP];
__device__ int    g_spillcnt;

__constant__ float c_knots[12] = {0.f,0.f,0.f,0.f,1.f,2.f,4.f,8.f,16.f,16.f,16.f,16.f};

// ---------------------------------------------------------------------------
// Launch 1: zero bin counters + Cox-de Boor basis (block 0, threads 0-7)
// ---------------------------------------------------------------------------
__global__ void setup_kernel(const float* __restrict__ t_in) {
    int g = blockIdx.x * blockDim.x + threadIdx.x;
    if (g < NB) g_cnt[g] = 0;
    if (g == 0) g_spillcnt = 0;

    if (blockIdx.x == 0 && threadIdx.x < T_) {
        int ti = threadIdx.x;
        float t = t_in[ti];
        float N[11];
        #pragma unroll
        for (int i = 0; i < 11; i++) {
            float l = c_knots[i], r = c_knots[i + 1];
            bool m = (i < 10) ? (t >= l && t < r) : (t >= l && t <= r);
            N[i] = m ? 1.f : 0.f;
        }
        #pragma unroll
        for (int p = 1; p <= 3; p++) {
            float Nn[11];
            for (int i = 0; i < 11 - p; i++) {
                float l = c_knots[i], mid = c_knots[i + p];
                float rr = c_knots[i + 1], fr = c_knots[i + p + 1];
                float term = 0.f;
                if (mid > l)  term += (t - l) / (mid - l) * N[i];
                if (fr > rr)  term += (fr - t) / (fr - rr) * N[i + 1];
                Nn[i] = term;
            }
            for (int i = 0; i < 11 - p; i++) N[i] = Nn[i];
        }
        #pragma unroll
        for (int b = 0; b < B_; b++) g_basis[ti * B_ + b] = N[b];
    }
}

// ---------------------------------------------------------------------------
// Launch 2: fused precompute for all 3 lattices
//   lat[v][t] = static[:,v] + sum_b basis[t,b]*coef[:,v,b]   (float4 over k)
// ---------------------------------------------------------------------------
__device__ __forceinline__ void pre_one(const float* __restrict__ stat,
                                        const float* __restrict__ coef,
                                        float4* __restrict__ lat, int Nvox, int v) {
    if (v >= Nvox) return;
    float bas[T_ * B_];
    #pragma unroll
    for (int i = 0; i < T_ * B_; i++) bas[i] = g_basis[i];

    float st[K_];
    #pragma unroll
    for (int k = 0; k < K_; k++) st[k] = stat[k * Nvox + v];

    float cf[K_][B_];
    #pragma unroll
    for (int k = 0; k < K_; k++) {
        const float4* cp = reinterpret_cast<const float4*>(coef + ((size_t)(k * Nvox) + v) * B_);
        float4 c0 = cp[0], c1 = cp[1];
        cf[k][0] = c0.x; cf[k][1] = c0.y; cf[k][2] = c0.z; cf[k][3] = c0.w;
        cf[k][4] = c1.x; cf[k][5] = c1.y; cf[k][6] = c1.z; cf[k][7] = c1.w;
    }
    #pragma unroll
    for (int t = 0; t < T_; t++) {
        float o[K_];
        #pragma unroll
        for (int k = 0; k < K_; k++) {
            float s = st[k];
            #pragma unroll
            for (int b = 0; b < B_; b++) s = fmaf(bas[t * B_ + b], cf[k][b], s);
            o[k] = s;
        }
        lat[(size_t)v * 8 + t] = make_float4(o[0], o[1], o[2], o[3]);
    }
}

__global__ void preall_kernel(const float* __restrict__ st0, const float* __restrict__ cf0,
                              const float* __restrict__ st1, const float* __restrict__ cf1,
                              const float* __restrict__ st2, const float* __restrict__ cf2) {
    int b = blockIdx.x, tid = threadIdx.x;
    if (b < 4)        pre_one(st0, cf0, g_lat0, 512,   b * 128 + tid);
    else if (b < 36)  pre_one(st1, cf1, g_lat1, 4096,  (b - 4) * 128 + tid);
    else              pre_one(st2, cf2, g_lat2, 32768, (b - 36) * 128 + tid);
}

// ---------------------------------------------------------------------------
// Launch 3: scatter points into fixed-capacity cell buckets (+ spill list)
// ---------------------------------------------------------------------------
__global__ void scatter_kernel(const float* __restrict__ coords, int P) {
    int p = blockIdx.x * blockDim.x + threadIdx.x;
    if (p >= P) return;
    float px = coords[3 * p], py = coords[3 * p + 1], pz = coords[3 * p + 2];
    int fx = min(max((int)floorf(px), 0), NCELL - 1);
    int fy = min(max((int)floorf(py), 0), NCELL - 1);
    int fz = min(max((int)floorf(pz), 0), NCELL - 1);
    int bin = (fx * NCELL + fy) * NCELL + fz;
    float4 rec = make_float4(px, py, pz, __int_as_float(p));
    int slot = atomicAdd(&g_cnt[bin], 1);
    if (slot < CAP) {
        g_bucket[bin * CAP + slot] = rec;
    } else {
        int s = atomicAdd(&g_spillcnt, 1);
        if (s < SPILLCAP) g_spill[s] = rec;
    }
}

// ---------------------------------------------------------------------------
// Launch 4 (PROFILED): cooperative tricubic gather.
// 8 lanes per point (lane tl owns t-slice tl); 4 points per warp, all from the
// SAME fine cell (bucket) -> every tap LDG has all 32 lanes on one 128B line.
// ---------------------------------------------------------------------------
__device__ __forceinline__ void cubw(float u, float w[4]) {
    float u2 = u * u, u3 = u2 * u;
    w[0] = (1.f / 6.f) * (1.f - 3.f * u + 3.f * u2 - u3);
    w[1] = (1.f / 6.f) * (4.f - 6.f * u2 + 3.f * u3);
    w[2] = (1.f / 6.f) * (1.f + 3.f * u + 3.f * u2 - 3.f * u3);
    w[3] = (1.f / 6.f) * u3;
}

__device__ __forceinline__ unsigned long long pack2(float w) {
    unsigned long long r;
    unsigned int wi = __float_as_uint(w);
    asm("mov.b64 %0, {%1, %1};" : "=l"(r) : "r"(wi));
    return r;
}

__device__ __forceinline__ unsigned long long mul2(unsigned long long a, unsigned long long b) {
    unsigned long long r;
    asm("mul.rn.f32x2 %0, %1, %2;" : "=l"(r) : "l"(a), "l"(b));
    return r;
}

__device__ __forceinline__ void ffma2(unsigned long long& d,
                                      unsigned long long a,
                                      unsigned long long b) {
    asm("fma.rn.f32x2 %0, %1, %2, %0;" : "+l"(d) : "l"(a), "l"(b));
}

__device__ __forceinline__ void accum_lattice_coop(const float4* __restrict__ lat, int n,
                                                   float scale, float px, float py, float pz,
                                                   int tl, unsigned long long acc[2]) {
    float cx = px * scale, cy = py * scale, cz = pz * scale;
    float fx = floorf(cx), fy = floorf(cy), fz = floorf(cz);
    int ix = (int)fx - 1, iy = (int)fy - 1, iz = (int)fz - 1;
    float wx[4], wy[4], wz[4];
    cubw(cx - fx, wx); cubw(cy - fy, wy); cubw(cz - fz, wz);
    unsigned long long wz2[4];
    int X[4], Y[4], zoff[4];
    #pragma unroll
    for (int a = 0; a < 4; a++) {
        X[a] = min(max(ix + a, 0), n - 1);
        Y[a] = min(max(iy + a, 0), n - 1);
        zoff[a] = min(max(iz + a, 0), n - 1) * 8;   // float4 units
        wz2[a] = pack2(wz[a]);
    }
    #pragma unroll
    for (int a = 0; a < 4; a++) {
        int xb = X[a] * n;
        #pragma unroll
        for (int b = 0; b < 4; b++) {
            unsigned long long wab2 = pack2(wx[a] * wy[b]);
            const ulonglong2* rowp =
                reinterpret_cast<const ulonglong2*>(lat + ((size_t)(xb + Y[b]) * n) * 8 + tl);
            #pragma unroll
            for (int c = 0; c < 4; c++) {
                unsigned long long w2 = mul2(wab2, wz2[c]);
                ulonglong2 v = rowp[zoff[c]];
                ffma2(acc[0], v.x, w2);
                ffma2(acc[1], v.y, w2);
            }
        }
    }
}

__device__ __forceinline__ void do_point(float4 s, int tl, int P,
                                         ulonglong2* __restrict__ out, bool active) {
    unsigned long long acc[2] = {0ULL, 0ULL};
    accum_lattice_coop(g_lat0,  8,  7.f / 31.f, s.x, s.y, s.z, tl, acc);
    accum_lattice_coop(g_lat1, 16, 15.f / 31.f, s.x, s.y, s.z, tl, acc);
    accum_lattice_coop(g_lat2, 32, 31.f / 31.f, s.x, s.y, s.z, tl, acc);
    if (active) {
        int orig = __float_as_int(s.w);
        ulonglong2 o; o.x = acc[0]; o.y = acc[1];
        out[(size_t)tl * P + orig] = o;
    }
}

__global__ void __launch_bounds__(256)
main_kernel(ulonglong2* __restrict__ out, int P) {
    int wid  = threadIdx.x >> 5;
    int lane = threadIdx.x & 31;
    int sub  = lane >> 3;     // point slot within warp (0..3)
    int tl   = lane & 7;      // time slot (0..7)

    if (blockIdx.x < BIN_BLOCKS) {
        int bin = blockIdx.x * 8 + wid;
        if (bin >= NB) return;
        int c = min(g_cnt[bin], CAP);
        for (int base = 0; base < c; base += 4) {
            int slot = base + sub;
            bool active = slot < c;
            float4 s = g_bucket[bin * CAP + min(slot, c - 1)];  // clamp: duplicate last point
            do_point(s, tl, P, out, active);
        }
    } else {
        int spillN = min(g_spillcnt, SPILLCAP);
        int w = (blockIdx.x - BIN_BLOCKS) * 8 + wid;
        for (int i = w * 4 + sub; i < spillN; i += SPILL_STRIDE) {
            float4 s = g_spill[i];
            do_point(s, tl, P, out, true);
        }
    }
}

// ---------------------------------------------------------------------------
extern "C" void kernel_launch(void* const* d_in, const int* in_sizes, int n_in,
                              void* d_out, int out_size) {
    // metadata order: 0:t 1:coords 2:static_0 3:coeffs_0 4:static_1 5:coeffs_1
    //                 6:static_2 7:coeffs_2
    const float* t_in   = (const float*)d_in[0];
    const float* coords = (const float*)d_in[1];
    const float* st0 = (const float*)d_in[2];
    const float* cf0 = (const float*)d_in[3];
    const float* st1 = (const float*)d_in[4];
    const float* cf1 = (const float*)d_in[5];
    const float* st2 = (const float*)d_in[6];
    const float* cf2 = (const float*)d_in[7];
    int P = in_sizes[1] / 3;
    if (P > MAXP) P = MAXP;

    setup_kernel<<<(NB + 255) / 256, 256>>>(t_in);                       // launch 1
    preall_kernel<<<292, 128>>>(st0, cf0, st1, cf1, st2, cf2);           // launch 2
    scatter_kernel<<<(P + 255) / 256, 256>>>(coords, P);                 // launch 3
    main_kernel<<<BIN_BLOCKS + SPILL_BLOCKS, 256>>>((ulonglong2*)d_out, P); // launch 4 (profiled)
}

// round 7
// speedup vs baseline: 6.4914x; 1.2896x over previous
#include <cuda_runtime.h>
#include <cuda_fp16.h>

#define T_ 8
#define K_ 4
#define B_ 8
#define MAXP 262144
#define NCELL 31
#define NB (NCELL * NCELL * NCELL)   // 29791 bins
#define CAP 16
#define SPILLCAP 32768
#define BIN_BLOCKS ((NB + 7) / 8)    // 3724 (8 warps/block, warp per bin)
#define SPILL_BLOCKS 64
#define SPILL_STRIDE (SPILL_BLOCKS * 8 * 4)

// Per-voxel time-expanded lattices in FP16:
// slice (voxel v, t) = uint2 = { half2(k0,k1), half2(k2,k3) } -> voxel line = 64 B
__device__ uint2 g_lat0h[512 * 8];
__device__ uint2 g_lat1h[4096 * 8];
__device__ uint2 g_lat2h[32768 * 8];
__device__ float g_basis[T_ * B_];

// Scan-free binning
__device__ float4 g_bucket[NB * CAP];   // (x,y,z, orig idx bits)
__device__ int    g_cnt[NB];
__device__ float4 g_spill[SPILLCAP];
__device__ int    g_spillcnt;

__constant__ float c_knots[12] = {0.f,0.f,0.f,0.f,1.f,2.f,4.f,8.f,16.f,16.f,16.f,16.f};

// ---------------------------------------------------------------------------
// Launch 1: zero bin counters + Cox-de Boor basis (block 0, threads 0-7)
// ---------------------------------------------------------------------------
__global__ void setup_kernel(const float* __restrict__ t_in) {
    int g = blockIdx.x * blockDim.x + threadIdx.x;
    if (g < NB) g_cnt[g] = 0;
    if (g == 0) g_spillcnt = 0;

    if (blockIdx.x == 0 && threadIdx.x < T_) {
        int ti = threadIdx.x;
        float t = t_in[ti];
        float N[11];
        #pragma unroll
        for (int i = 0; i < 11; i++) {
            float l = c_knots[i], r = c_knots[i + 1];
            bool m = (i < 10) ? (t >= l && t < r) : (t >= l && t <= r);
            N[i] = m ? 1.f : 0.f;
        }
        #pragma unroll
        for (int p = 1; p <= 3; p++) {
            float Nn[11];
            for (int i = 0; i < 11 - p; i++) {
                float l = c_knots[i], mid = c_knots[i + p];
                float rr = c_knots[i + 1], fr = c_knots[i + p + 1];
                float term = 0.f;
                if (mid > l)  term += (t - l) / (mid - l) * N[i];
                if (fr > rr)  term += (fr - t) / (fr - rr) * N[i + 1];
                Nn[i] = term;
            }
            for (int i = 0; i < 11 - p; i++) N[i] = Nn[i];
        }
        #pragma unroll
        for (int b = 0; b < B_; b++) g_basis[ti * B_ + b] = N[b];
    }
}

// ---------------------------------------------------------------------------
// Launch 2: fused precompute for all 3 lattices (fp32 math, fp16 store)
// ---------------------------------------------------------------------------
__device__ __forceinline__ unsigned h2u(__half2 h) {
    return *reinterpret_cast<unsigned*>(&h);
}
__device__ __forceinline__ __half2 u2h(unsigned u) {
    __half2 h; *reinterpret_cast<unsigned*>(&h) = u; return h;
}

__device__ __forceinline__ void pre_one(const float* __restrict__ stat,
                                        const float* __restrict__ coef,
                                        uint2* __restrict__ lat, int Nvox, int v) {
    if (v >= Nvox) return;
    float bas[T_ * B_];
    #pragma unroll
    for (int i = 0; i < T_ * B_; i++) bas[i] = g_basis[i];

    float st[K_];
    #pragma unroll
    for (int k = 0; k < K_; k++) st[k] = stat[k * Nvox + v];

    float cf[K_][B_];
    #pragma unroll
    for (int k = 0; k < K_; k++) {
        const float4* cp = reinterpret_cast<const float4*>(coef + ((size_t)(k * Nvox) + v) * B_);
        float4 c0 = cp[0], c1 = cp[1];
        cf[k][0] = c0.x; cf[k][1] = c0.y; cf[k][2] = c0.z; cf[k][3] = c0.w;
        cf[k][4] = c1.x; cf[k][5] = c1.y; cf[k][6] = c1.z; cf[k][7] = c1.w;
    }
    #pragma unroll
    for (int t = 0; t < T_; t++) {
        float o[K_];
        #pragma unroll
        for (int k = 0; k < K_; k++) {
            float s = st[k];
            #pragma unroll
            for (int b = 0; b < B_; b++) s = fmaf(bas[t * B_ + b], cf[k][b], s);
            o[k] = s;
        }
        uint2 r;
        r.x = h2u(__floats2half2_rn(o[0], o[1]));
        r.y = h2u(__floats2half2_rn(o[2], o[3]));
        lat[(size_t)v * 8 + t] = r;
    }
}

__global__ void preall_kernel(const float* __restrict__ st0, const float* __restrict__ cf0,
                              const float* __restrict__ st1, const float* __restrict__ cf1,
                              const float* __restrict__ st2, const float* __restrict__ cf2) {
    int b = blockIdx.x, tid = threadIdx.x;
    if (b < 4)        pre_one(st0, cf0, g_lat0h, 512,   b * 128 + tid);
    else if (b < 36)  pre_one(st1, cf1, g_lat1h, 4096,  (b - 4) * 128 + tid);
    else              pre_one(st2, cf2, g_lat2h, 32768, (b - 36) * 128 + tid);
}

// ---------------------------------------------------------------------------
// Launch 3: scatter points into fixed-capacity cell buckets (+ spill list)
// ---------------------------------------------------------------------------
__global__ void scatter_kernel(const float* __restrict__ coords, int P) {
    int p = blockIdx.x * blockDim.x + threadIdx.x;
    if (p >= P) return;
    float px = coords[3 * p], py = coords[3 * p + 1], pz = coords[3 * p + 2];
    int fx = min(max((int)floorf(px), 0), NCELL - 1);
    int fy = min(max((int)floorf(py), 0), NCELL - 1);
    int fz = min(max((int)floorf(pz), 0), NCELL - 1);
    int bin = (fx * NCELL + fy) * NCELL + fz;
    float4 rec = make_float4(px, py, pz, __int_as_float(p));
    int slot = atomicAdd(&g_cnt[bin], 1);
    if (slot < CAP) {
        g_bucket[bin * CAP + slot] = rec;
    } else {
        int s = atomicAdd(&g_spillcnt, 1);
        if (s < SPILLCAP) g_spill[s] = rec;
    }
}

// ---------------------------------------------------------------------------
// Launch 4 (PROFILED): cooperative tricubic gather, fp16 taps.
// 8 lanes per point (lane tl owns t-slice tl = 8 B); 4 points per warp from
// the same fine cell. Tap load = LDG.64 (2 wavefronts vs 4 for fp32).
// z-row partial sums accumulate in half2 (HFMA2, no converts per tap);
// converted once per (a,b) row and folded into fp32x2 accumulators.
// ---------------------------------------------------------------------------
__device__ __forceinline__ void cubw(float u, float w[4]) {
    float u2 = u * u, u3 = u2 * u;
    w[0] = (1.f / 6.f) * (1.f - 3.f * u + 3.f * u2 - u3);
    w[1] = (1.f / 6.f) * (4.f - 6.f * u2 + 3.f * u3);
    w[2] = (1.f / 6.f) * (1.f + 3.f * u + 3.f * u2 - 3.f * u3);
    w[3] = (1.f / 6.f) * u3;
}

__device__ __forceinline__ unsigned long long pack2(float w) {
    unsigned long long r;
    unsigned int wi = __float_as_uint(w);
    asm("mov.b64 %0, {%1, %1};" : "=l"(r) : "r"(wi));
    return r;
}

__device__ __forceinline__ unsigned long long pack2f(float a, float b) {
    unsigned long long r;
    asm("mov.b64 %0, {%1, %2};" : "=l"(r) : "f"(a), "f"(b));
    return r;
}

__device__ __forceinline__ void ffma2(unsigned long long& d,
                                      unsigned long long a,
                                      unsigned long long b) {
    asm("fma.rn.f32x2 %0, %1, %2, %0;" : "+l"(d) : "l"(a), "l"(b));
}

__device__ __forceinline__ void accum_lattice_h(const uint2* __restrict__ lat, int n,
                                                float scale, float px, float py, float pz,
                                                int tl, unsigned long long acc[2]) {
    float cx = px * scale, cy = py * scale, cz = pz * scale;
    float fx = floorf(cx), fy = floorf(cy), fz = floorf(cz);
    int ix = (int)fx - 1, iy = (int)fy - 1, iz = (int)fz - 1;
    float wx[4], wy[4], wz[4];
    cubw(cx - fx, wx); cubw(cy - fy, wy); cubw(cz - fz, wz);
    __half2 wzh[4];
    int X[4], Y[4], zoff[4];
    #pragma unroll
    for (int a = 0; a < 4; a++) {
        X[a] = min(max(ix + a, 0), n - 1);
        Y[a] = min(max(iy + a, 0), n - 1);
        zoff[a] = min(max(iz + a, 0), n - 1) * 8;   // uint2 units
        wzh[a] = __floats2half2_rn(wz[a], wz[a]);
    }
    const __half2 zero = __floats2half2_rn(0.f, 0.f);
    #pragma unroll
    for (int a = 0; a < 4; a++) {
        int xb = X[a] * n;
        #pragma unroll
        for (int b = 0; b < 4; b++) {
            unsigned long long wab2 = pack2(wx[a] * wy[b]);
            const uint2* rowp = lat + ((size_t)(xb + Y[b]) * n) * 8 + tl;
            __half2 s01 = zero, s23 = zero;
            #pragma unroll
            for (int c = 0; c < 4; c++) {
                uint2 h = rowp[zoff[c]];
                s01 = __hfma2(u2h(h.x), wzh[c], s01);
                s23 = __hfma2(u2h(h.y), wzh[c], s23);
            }
            float2 f01 = __half22float2(s01);
            float2 f23 = __half22float2(s23);
            ffma2(acc[0], pack2f(f01.x, f01.y), wab2);
            ffma2(acc[1], pack2f(f23.x, f23.y), wab2);
        }
    }
}

__device__ __forceinline__ void do_point(float4 s, int tl, int P,
                                         ulonglong2* __restrict__ out, bool active) {
    unsigned long long acc[2] = {0ULL, 0ULL};
    accum_lattice_h(g_lat0h,  8,  7.f / 31.f, s.x, s.y, s.z, tl, acc);
    accum_lattice_h(g_lat1h, 16, 15.f / 31.f, s.x, s.y, s.z, tl, acc);
    accum_lattice_h(g_lat2h, 32, 31.f / 31.f, s.x, s.y, s.z, tl, acc);
    if (active) {
        int orig = __float_as_int(s.w);
        ulonglong2 o; o.x = acc[0]; o.y = acc[1];
        out[(size_t)tl * P + orig] = o;
    }
}

__global__ void __launch_bounds__(256)
main_kernel(ulonglong2* __restrict__ out, int P) {
    int wid  = threadIdx.x >> 5;
    int lane = threadIdx.x & 31;
    int sub  = lane >> 3;     // point slot within warp (0..3)
    int tl   = lane & 7;      // time slot (0..7)

    if (blockIdx.x < BIN_BLOCKS) {
        int bin = blockIdx.x * 8 + wid;
        if (bin >= NB) return;
        int c = min(g_cnt[bin], CAP);
        for (int base = 0; base < c; base += 4) {
            int slot = base + sub;
            bool active = slot < c;
            float4 s = g_bucket[bin * CAP + min(slot, c - 1)];  // clamp: duplicate last point
            do_point(s, tl, P, out, active);
        }
    } else {
        int spillN = min(g_spillcnt, SPILLCAP);
        int w = (blockIdx.x - BIN_BLOCKS) * 8 + wid;
        for (int i = w * 4 + sub; i < spillN; i += SPILL_STRIDE) {
            float4 s = g_spill[i];
            do_point(s, tl, P, out, true);
        }
    }
}

// ---------------------------------------------------------------------------
extern "C" void kernel_launch(void* const* d_in, const int* in_sizes, int n_in,
                              void* d_out, int out_size) {
    // metadata order: 0:t 1:coords 2:static_0 3:coeffs_0 4:static_1 5:coeffs_1
    //                 6:static_2 7:coeffs_2
    const float* t_in   = (const float*)d_in[0];
    const float* coords = (const float*)d_in[1];
    const float* st0 = (const float*)d_in[2];
    const float* cf0 = (const float*)d_in[3];
    const float* st1 = (const float*)d_in[4];
    const float* cf1 = (const float*)d_in[5];
    const float* st2 = (const float*)d_in[6];
    const float* cf2 = (const float*)d_in[7];
    int P = in_sizes[1] / 3;
    if (P > MAXP) P = MAXP;

    setup_kernel<<<(NB + 255) / 256, 256>>>(t_in);                       // launch 1
    preall_kernel<<<292, 128>>>(st0, cf0, st1, cf1, st2, cf2);           // launch 2
    scatter_kernel<<<(P + 255) / 256, 256>>>(coords, P);                 // launch 3
    main_kernel<<<BIN_BLOCKS + SPILL_BLOCKS, 256>>>((ulonglong2*)d_out, P); // launch 4 (profiled)
}

// round 8
// speedup vs baseline: 8.0754x; 1.2440x over previous
#include <cuda_runtime.h>
#include <cuda_fp16.h>

#define T_ 8
#define K_ 4
#define B_ 8
#define MAXP 262144
#define NCELL 31
#define NB (NCELL * NCELL * NCELL)   // 29791 bins

// Per-voxel time-expanded lattices in FP16:
// slice (voxel v, t) = uint2 = { half2(k0,k1), half2(k2,k3) } -> voxel line = 64 B
__device__ uint2 g_lat0h[512 * 8];
__device__ uint2 g_lat1h[4096 * 8];
__device__ uint2 g_lat2h[32768 * 8];
__device__ float g_basis[T_ * B_];

// Counting sort
__device__ float4 g_sorted[MAXP];    // (x, y, z, orig idx bits), bin-ordered dense
__device__ int    g_hist[NB];
__device__ int    g_base[NB];
__device__ int    g_cur[NB];

__constant__ float c_knots[12] = {0.f,0.f,0.f,0.f,1.f,2.f,4.f,8.f,16.f,16.f,16.f,16.f};

// ---------------------------------------------------------------------------
// Launch 1: zero hist/cur + Cox-de Boor basis (block 0, threads 0-7)
// ---------------------------------------------------------------------------
__global__ void setup_kernel(const float* __restrict__ t_in) {
    int g = blockIdx.x * blockDim.x + threadIdx.x;
    if (g < NB) { g_hist[g] = 0; g_cur[g] = 0; }

    if (blockIdx.x == 0 && threadIdx.x < T_) {
        int ti = threadIdx.x;
        float t = t_in[ti];
        float N[11];
        #pragma unroll
        for (int i = 0; i < 11; i++) {
            float l = c_knots[i], r = c_knots[i + 1];
            bool m = (i < 10) ? (t >= l && t < r) : (t >= l && t <= r);
            N[i] = m ? 1.f : 0.f;
        }
        #pragma unroll
        for (int p = 1; p <= 3; p++) {
            float Nn[11];
            for (int i = 0; i < 11 - p; i++) {
                float l = c_knots[i], mid = c_knots[i + p];
                float rr = c_knots[i + 1], fr = c_knots[i + p + 1];
                float term = 0.f;
                if (mid > l)  term += (t - l) / (mid - l) * N[i];
                if (fr > rr)  term += (fr - t) / (fr - rr) * N[i + 1];
                Nn[i] = term;
            }
            for (int i = 0; i < 11 - p; i++) N[i] = Nn[i];
        }
        #pragma unroll
        for (int b = 0; b < B_; b++) g_basis[ti * B_ + b] = N[b];
    }
}

// ---------------------------------------------------------------------------
// Launch 2: fused precompute for all 3 lattices (fp32 math, fp16 store)
// ---------------------------------------------------------------------------
__device__ __forceinline__ unsigned h2u(__half2 h) {
    return *reinterpret_cast<unsigned*>(&h);
}
__device__ __forceinline__ __half2 u2h(unsigned u) {
    __half2 h; *reinterpret_cast<unsigned*>(&h) = u; return h;
}

__device__ __forceinline__ void pre_one(const float* __restrict__ stat,
                                        const float* __restrict__ coef,
                                        uint2* __restrict__ lat, int Nvox, int v) {
    if (v >= Nvox) return;
    float bas[T_ * B_];
    #pragma unroll
    for (int i = 0; i < T_ * B_; i++) bas[i] = g_basis[i];

    float st[K_];
    #pragma unroll
    for (int k = 0; k < K_; k++) st[k] = stat[k * Nvox + v];

    float cf[K_][B_];
    #pragma unroll
    for (int k = 0; k < K_; k++) {
        const float4* cp = reinterpret_cast<const float4*>(coef + ((size_t)(k * Nvox) + v) * B_);
        float4 c0 = cp[0], c1 = cp[1];
        cf[k][0] = c0.x; cf[k][1] = c0.y; cf[k][2] = c0.z; cf[k][3] = c0.w;
        cf[k][4] = c1.x; cf[k][5] = c1.y; cf[k][6] = c1.z; cf[k][7] = c1.w;
    }
    #pragma unroll
    for (int t = 0; t < T_; t++) {
        float o[K_];
        #pragma unroll
        for (int k = 0; k < K_; k++) {
            float s = st[k];
            #pragma unroll
            for (int b = 0; b < B_; b++) s = fmaf(bas[t * B_ + b], cf[k][b], s);
            o[k] = s;
        }
        uint2 r;
        r.x = h2u(__floats2half2_rn(o[0], o[1]));
        r.y = h2u(__floats2half2_rn(o[2], o[3]));
        lat[(size_t)v * 8 + t] = r;
    }
}

__global__ void preall_kernel(const float* __restrict__ st0, const float* __restrict__ cf0,
                              const float* __restrict__ st1, const float* __restrict__ cf1,
                              const float* __restrict__ st2, const float* __restrict__ cf2) {
    int b = blockIdx.x, tid = threadIdx.x;
    if (b < 4)        pre_one(st0, cf0, g_lat0h, 512,   b * 128 + tid);
    else if (b < 36)  pre_one(st1, cf1, g_lat1h, 4096,  (b - 4) * 128 + tid);
    else              pre_one(st2, cf2, g_lat2h, 32768, (b - 36) * 128 + tid);
}

// ---------------------------------------------------------------------------
// Counting sort by fine-lattice cell
// ---------------------------------------------------------------------------
__device__ __forceinline__ int cell_of(float px, float py, float pz) {
    int fx = min(max((int)floorf(px), 0), NCELL - 1);
    int fy = min(max((int)floorf(py), 0), NCELL - 1);
    int fz = min(max((int)floorf(pz), 0), NCELL - 1);
    return (fx * NCELL + fy) * NCELL + fz;
}

__global__ void hist_kernel(const float* __restrict__ coords, int P) {
    int p = blockIdx.x * blockDim.x + threadIdx.x;
    if (p >= P) return;
    atomicAdd(&g_hist[cell_of(coords[3*p], coords[3*p+1], coords[3*p+2])], 1);
}

__global__ void scan_kernel() {
    __shared__ int part[1024];
    int tid = threadIdx.x;
    const int CH = (NB + 1023) / 1024;        // 30
    int start = tid * CH, end = min(start + CH, NB);
    int s = 0;
    for (int i = start; i < end; i++) s += g_hist[i];
    part[tid] = s;
    __syncthreads();
    for (int off = 1; off < 1024; off <<= 1) {
        int v = (tid >= off) ? part[tid - off] : 0;
        __syncthreads();
        part[tid] += v;
        __syncthreads();
    }
    int run = part[tid] - s;                  // exclusive prefix
    for (int i = start; i < end; i++) { g_base[i] = run; run += g_hist[i]; }
}

__global__ void scatter_kernel(const float* __restrict__ coords, int P) {
    int p = blockIdx.x * blockDim.x + threadIdx.x;
    if (p >= P) return;
    float px = coords[3*p], py = coords[3*p+1], pz = coords[3*p+2];
    int bin = cell_of(px, py, pz);
    int pos = g_base[bin] + atomicAdd(&g_cur[bin], 1);
    g_sorted[pos] = make_float4(px, py, pz, __int_as_float(p));
}

// ---------------------------------------------------------------------------
// Launch 6: cooperative tricubic gather, fp16 taps.
// 4 lanes per point (lane tq owns t-pair {2tq, 2tq+1} = 16 B voxel slice);
// 8 consecutive SORTED points per warp -> uniform work, max line sharing.
// Tap = 1 LDG.128 + 4 HFMA2 covering 8 points. z-row sums in half2,
// converted once per (a,b) row and folded into fp32x2 accumulators.
// ---------------------------------------------------------------------------
__device__ __forceinline__ void cubw(float u, float w[4]) {
    float u2 = u * u, u3 = u2 * u;
    w[0] = (1.f / 6.f) * (1.f - 3.f * u + 3.f * u2 - u3);
    w[1] = (1.f / 6.f) * (4.f - 6.f * u2 + 3.f * u3);
    w[2] = (1.f / 6.f) * (1.f + 3.f * u + 3.f * u2 - 3.f * u3);
    w[3] = (1.f / 6.f) * u3;
}

__device__ __forceinline__ unsigned long long pack2(float w) {
    unsigned long long r;
    unsigned int wi = __float_as_uint(w);
    asm("mov.b64 %0, {%1, %1};" : "=l"(r) : "r"(wi));
    return r;
}

__device__ __forceinline__ unsigned long long pack2f(float a, float b) {
    unsigned long long r;
    asm("mov.b64 %0, {%1, %2};" : "=l"(r) : "f"(a), "f"(b));
    return r;
}

__device__ __forceinline__ void ffma2(unsigned long long& d,
                                      unsigned long long a,
                                      unsigned long long b) {
    asm("fma.rn.f32x2 %0, %1, %2, %0;" : "+l"(d) : "l"(a), "l"(b));
}

__device__ __forceinline__ void accum_lattice_h4(const uint2* __restrict__ lat, int n,
                                                 float scale, float px, float py, float pz,
                                                 int tq, unsigned long long acc[4]) {
    float cx = px * scale, cy = py * scale, cz = pz * scale;
    float fx = floorf(cx), fy = floorf(cy), fz = floorf(cz);
    int ix = (int)fx - 1, iy = (int)fy - 1, iz = (int)fz - 1;
    float wx[4], wy[4], wz[4];
    cubw(cx - fx, wx); cubw(cy - fy, wy); cubw(cz - fz, wz);
    __half2 wzh[4];
    int X[4], Y[4], zoff[4];
    #pragma unroll
    for (int a = 0; a < 4; a++) {
        X[a] = min(max(ix + a, 0), n - 1);
        Y[a] = min(max(iy + a, 0), n - 1);
        zoff[a] = min(max(iz + a, 0), n - 1) * 8;   // uint2 units
        wzh[a] = __floats2half2_rn(wz[a], wz[a]);
    }
    const __half2 zero = __floats2half2_rn(0.f, 0.f);
    #pragma unroll
    for (int a = 0; a < 4; a++) {
        int xb = X[a] * n;
        #pragma unroll
        for (int b = 0; b < 4; b++) {
            unsigned long long wab2 = pack2(wx[a] * wy[b]);
            // base of this (x,y) z-column, at this lane's 16B t-pair slice
            const uint2* base = lat + ((size_t)(xb + Y[b]) * n) * 8 + 2 * tq;
            __half2 sA0 = zero, sA1 = zero, sB0 = zero, sB1 = zero;
            #pragma unroll
            for (int c = 0; c < 4; c++) {
                uint4 h = *reinterpret_cast<const uint4*>(base + zoff[c]);
                sA0 = __hfma2(u2h(h.x), wzh[c], sA0);
                sA1 = __hfma2(u2h(h.y), wzh[c], sA1);
                sB0 = __hfma2(u2h(h.z), wzh[c], sB0);
                sB1 = __hfma2(u2h(h.w), wzh[c], sB1);
            }
            float2 a0 = __half22float2(sA0);
            float2 a1 = __half22float2(sA1);
            float2 b0 = __half22float2(sB0);
            float2 b1 = __half22float2(sB1);
            ffma2(acc[0], pack2f(a0.x, a0.y), wab2);
            ffma2(acc[1], pack2f(a1.x, a1.y), wab2);
            ffma2(acc[2], pack2f(b0.x, b0.y), wab2);
            ffma2(acc[3], pack2f(b1.x, b1.y), wab2);
        }
    }
}

__global__ void __launch_bounds__(256)
main_kernel(ulonglong2* __restrict__ out, int P) {
    int warp = blockIdx.x * (blockDim.x >> 5) + (threadIdx.x >> 5);
    int lane = threadIdx.x & 31;
    int sub  = lane >> 2;     // point slot within warp (0..7)
    int tq   = lane & 3;      // t-pair: owns t = 2tq, 2tq+1
    int p = warp * 8 + sub;
    bool active = p < P;

    float4 s = g_sorted[min(p, P - 1)];

    unsigned long long acc[4] = {0ULL, 0ULL, 0ULL, 0ULL};
    accum_lattice_h4(g_lat0h,  8,  7.f / 31.f, s.x, s.y, s.z, tq, acc);
    accum_lattice_h4(g_lat1h, 16, 15.f / 31.f, s.x, s.y, s.z, tq, acc);
    accum_lattice_h4(g_lat2h, 32, 31.f / 31.f, s.x, s.y, s.z, tq, acc);

    if (active) {
        int orig = __float_as_int(s.w);
        ulonglong2 oA; oA.x = acc[0]; oA.y = acc[1];   // t = 2tq
        ulonglong2 oB; oB.x = acc[2]; oB.y = acc[3];   // t = 2tq+1
        out[(size_t)(2 * tq)     * P + orig] = oA;
        out[(size_t)(2 * tq + 1) * P + orig] = oB;
    }
}

// ---------------------------------------------------------------------------
extern "C" void kernel_launch(void* const* d_in, const int* in_sizes, int n_in,
                              void* d_out, int out_size) {
    // metadata order: 0:t 1:coords 2:static_0 3:coeffs_0 4:static_1 5:coeffs_1
    //                 6:static_2 7:coeffs_2
    const float* t_in   = (const float*)d_in[0];
    const float* coords = (const float*)d_in[1];
    const float* st0 = (const float*)d_in[2];
    const float* cf0 = (const float*)d_in[3];
    const float* st1 = (const float*)d_in[4];
    const float* cf1 = (const float*)d_in[5];
    const float* st2 = (const float*)d_in[6];
    const float* cf2 = (const float*)d_in[7];
    int P = in_sizes[1] / 3;
    if (P > MAXP) P = MAXP;

    setup_kernel<<<(NB + 255) / 256, 256>>>(t_in);                 // 1
    preall_kernel<<<292, 128>>>(st0, cf0, st1, cf1, st2, cf2);     // 2
    hist_kernel<<<(P + 255) / 256, 256>>>(coords, P);              // 3
    scan_kernel<<<1, 1024>>>();                                    // 4
    scatter_kernel<<<(P + 255) / 256, 256>>>(coords, P);           // 5
    // 8 points per warp -> 64 points per 256-thread block
    main_kernel<<<(P + 63) / 64, 256>>>((ulonglong2*)d_out, P);    // 6
}

// round 9
// speedup vs baseline: 8.6813x; 1.0750x over previous
#include <cuda_runtime.h>
#include <cuda_fp16.h>

#define T_ 8
#define K_ 4
#define B_ 8
#define MAXP 262144
#define NCELL 31
#define NB (NCELL * NCELL * NCELL)   // 29791 bins
#define NBPAD 32768
#define PRE_BLOCKS 146               // 146*256 = 37376 = 512+4096+32768 voxels
#define ZERO_BLOCKS 32               // 32*256 threads x int4 = 32768 ints per array

// Per-voxel time-expanded lattices in FP16:
// slice (voxel v, t) = uint2 = { half2(k0,k1), half2(k2,k3) } -> voxel line = 64 B
__device__ uint2 g_lat0h[512 * 8];
__device__ uint2 g_lat1h[4096 * 8];
__device__ uint2 g_lat2h[32768 * 8];
__device__ float g_basis[T_ * B_];

// Counting sort (padded to 32768 for vector scan; extras stay zero)
__device__ float4 g_sorted[MAXP];
__device__ __align__(16) int g_hist[NBPAD];   // zero-init at load; re-zeroed each call by main tail
__device__ __align__(16) int g_base[NBPAD];
__device__ __align__(16) int g_cur[NBPAD];

__constant__ float c_knots[12] = {0.f,0.f,0.f,0.f,1.f,2.f,4.f,8.f,16.f,16.f,16.f,16.f};

// ---------------------------------------------------------------------------
__device__ __forceinline__ int cell_of(float px, float py, float pz) {
    int fx = min(max((int)floorf(px), 0), NCELL - 1);
    int fy = min(max((int)floorf(py), 0), NCELL - 1);
    int fz = min(max((int)floorf(pz), 0), NCELL - 1);
    return (fx * NCELL + fy) * NCELL + fz;
}

// ---------------------------------------------------------------------------
// Launch 1: histogram + Cox-de Boor basis (block 0, threads 0-7)
// (g_hist is guaranteed zero: zero-init at module load, re-zeroed by launch 4)
// ---------------------------------------------------------------------------
__global__ void k1_hist_basis(const float* __restrict__ t_in,
                              const float* __restrict__ coords, int P) {
    int p = blockIdx.x * blockDim.x + threadIdx.x;
    if (p < P)
        atomicAdd(&g_hist[cell_of(coords[3*p], coords[3*p+1], coords[3*p+2])], 1);

    if (blockIdx.x == 0 && threadIdx.x < T_) {
        int ti = threadIdx.x;
        float t = t_in[ti];
        float N[11];
        #pragma unroll
        for (int i = 0; i < 11; i++) {
            float l = c_knots[i], r = c_knots[i + 1];
            bool m = (i < 10) ? (t >= l && t < r) : (t >= l && t <= r);
            N[i] = m ? 1.f : 0.f;
        }
        #pragma unroll
        for (int q = 1; q <= 3; q++) {
            float Nn[11];
            for (int i = 0; i < 11 - q; i++) {
                float l = c_knots[i], mid = c_knots[i + q];
                float rr = c_knots[i + 1], fr = c_knots[i + q + 1];
                float term = 0.f;
                if (mid > l)  term += (t - l) / (mid - l) * N[i];
                if (fr > rr)  term += (fr - t) / (fr - rr) * N[i + 1];
                Nn[i] = term;
            }
            for (int i = 0; i < 11 - q; i++) N[i] = Nn[i];
        }
        #pragma unroll
        for (int b = 0; b < B_; b++) g_basis[ti * B_ + b] = N[b];
    }
}

// ---------------------------------------------------------------------------
// Launch 2: vectorized exclusive scan of g_hist -> g_base (32768 entries)
// 1024 threads x 32 bins each, int4 loads/stores, shfl warp scans.
// ---------------------------------------------------------------------------
__global__ void k2_scan() {
    __shared__ int wsum[32];
    int tid = threadIdx.x, lane = tid & 31, wid = tid >> 5;
    int4 v[8]; int s = 0;
    const int4* hp = reinterpret_cast<const int4*>(g_hist) + tid * 8;
    #pragma unroll
    for (int j = 0; j < 8; j++) { v[j] = hp[j]; s += v[j].x + v[j].y + v[j].z + v[j].w; }
    int incl = s;
    #pragma unroll
    for (int o = 1; o < 32; o <<= 1) { int t = __shfl_up_sync(~0u, incl, o); if (lane >= o) incl += t; }
    if (lane == 31) wsum[wid] = incl;
    __syncthreads();
    if (wid == 0) {
        int w = wsum[lane];
        int wi = w;
        #pragma unroll
        for (int o = 1; o < 32; o <<= 1) { int t = __shfl_up_sync(~0u, wi, o); if (lane >= o) wi += t; }
        wsum[lane] = wi - w;   // exclusive across warps
    }
    __syncthreads();
    int run = wsum[wid] + (incl - s);   // exclusive prefix of this thread's chunk
    int4* bp = reinterpret_cast<int4*>(g_base) + tid * 8;
    #pragma unroll
    for (int j = 0; j < 8; j++) {
        int4 o;
        o.x = run; run += v[j].x;
        o.y = run; run += v[j].y;
        o.z = run; run += v[j].z;
        o.w = run; run += v[j].w;
        bp[j] = o;
    }
}

// ---------------------------------------------------------------------------
// Launch 3: fused scatter + lattice precompute
// ---------------------------------------------------------------------------
__device__ __forceinline__ unsigned h2u(__half2 h) { return *reinterpret_cast<unsigned*>(&h); }
__device__ __forceinline__ __half2 u2h(unsigned u) { __half2 h; *reinterpret_cast<unsigned*>(&h) = u; return h; }

__device__ __forceinline__ void pre_one(const float* __restrict__ stat,
                                        const float* __restrict__ coef,
                                        uint2* __restrict__ lat, int Nvox, int v) {
    float bas[T_ * B_];
    #pragma unroll
    for (int i = 0; i < T_ * B_; i++) bas[i] = g_basis[i];

    float st[K_];
    #pragma unroll
    for (int k = 0; k < K_; k++) st[k] = stat[k * Nvox + v];

    float cf[K_][B_];
    #pragma unroll
    for (int k = 0; k < K_; k++) {
        const float4* cp = reinterpret_cast<const float4*>(coef + ((size_t)(k * Nvox) + v) * B_);
        float4 c0 = cp[0], c1 = cp[1];
        cf[k][0] = c0.x; cf[k][1] = c0.y; cf[k][2] = c0.z; cf[k][3] = c0.w;
        cf[k][4] = c1.x; cf[k][5] = c1.y; cf[k][6] = c1.z; cf[k][7] = c1.w;
    }
    #pragma unroll
    for (int t = 0; t < T_; t++) {
        float o[K_];
        #pragma unroll
        for (int k = 0; k < K_; k++) {
            float s = st[k];
            #pragma unroll
            for (int b = 0; b < B_; b++) s = fmaf(bas[t * B_ + b], cf[k][b], s);
            o[k] = s;
        }
        uint2 r;
        r.x = h2u(__floats2half2_rn(o[0], o[1]));
        r.y = h2u(__floats2half2_rn(o[2], o[3]));
        lat[(size_t)v * 8 + t] = r;
    }
}

__global__ void k3_scatter_pre(const float* __restrict__ st0, const float* __restrict__ cf0,
                               const float* __restrict__ st1, const float* __restrict__ cf1,
                               const float* __restrict__ st2, const float* __restrict__ cf2,
                               const float* __restrict__ coords, int P) {
    if (blockIdx.x < PRE_BLOCKS) {
        int v = blockIdx.x * 256 + threadIdx.x;
        if (v < 512)       pre_one(st0, cf0, g_lat0h, 512,   v);
        else if (v < 4608) pre_one(st1, cf1, g_lat1h, 4096,  v - 512);
        else               pre_one(st2, cf2, g_lat2h, 32768, v - 4608);
    } else {
        int p = (blockIdx.x - PRE_BLOCKS) * 256 + threadIdx.x;
        if (p >= P) return;
        float px = coords[3*p], py = coords[3*p+1], pz = coords[3*p+2];
        int bin = cell_of(px, py, pz);
        int pos = g_base[bin] + atomicAdd(&g_cur[bin], 1);
        g_sorted[pos] = make_float4(px, py, pz, __int_as_float(p));
    }
}

// ---------------------------------------------------------------------------
// Launch 4 (PROFILED): cooperative tricubic gather, fp16 taps.
// 4 lanes per point (lane tq owns t-pair = 16 B voxel slice); 8 sorted points
// per warp. Tail blocks re-zero g_hist/g_cur for the next graph replay.
// ---------------------------------------------------------------------------
__device__ __forceinline__ void cubw(float u, float w[4]) {
    float u2 = u * u, u3 = u2 * u;
    w[0] = (1.f / 6.f) * (1.f - 3.f * u + 3.f * u2 - u3);
    w[1] = (1.f / 6.f) * (4.f - 6.f * u2 + 3.f * u3);
    w[2] = (1.f / 6.f) * (1.f + 3.f * u + 3.f * u2 - 3.f * u3);
    w[3] = (1.f / 6.f) * u3;
}

__device__ __forceinline__ unsigned long long pack2(float w) {
    unsigned long long r;
    unsigned int wi = __float_as_uint(w);
    asm("mov.b64 %0, {%1, %1};" : "=l"(r) : "r"(wi));
    return r;
}

__device__ __forceinline__ unsigned long long pack2f(float a, float b) {
    unsigned long long r;
    asm("mov.b64 %0, {%1, %2};" : "=l"(r) : "f"(a), "f"(b));
    return r;
}

__device__ __forceinline__ void ffma2(unsigned long long& d,
                                      unsigned long long a,
                                      unsigned long long b) {
    asm("fma.rn.f32x2 %0, %1, %2, %0;" : "+l"(d) : "l"(a), "l"(b));
}

__device__ __forceinline__ void accum_lattice_h4(const uint2* __restrict__ lat, int n,
                                                 float scale, float px, float py, float pz,
                                                 int tq, unsigned long long acc[4]) {
    float cx = px * scale, cy = py * scale, cz = pz * scale;
    float fx = floorf(cx), fy = floorf(cy), fz = floorf(cz);
    int ix = (int)fx - 1, iy = (int)fy - 1, iz = (int)fz - 1;
    float wx[4], wy[4], wz[4];
    cubw(cx - fx, wx); cubw(cy - fy, wy); cubw(cz - fz, wz);
    __half2 wzh[4];
    int X[4], Y[4], zoff[4];
    #pragma unroll
    for (int a = 0; a < 4; a++) {
        X[a] = min(max(ix + a, 0), n - 1);
        Y[a] = min(max(iy + a, 0), n - 1);
        zoff[a] = min(max(iz + a, 0), n - 1) * 8;   // uint2 units
        wzh[a] = __floats2half2_rn(wz[a], wz[a]);
    }
    const __half2 zero = __floats2half2_rn(0.f, 0.f);
    #pragma unroll
    for (int a = 0; a < 4; a++) {
        int xb = X[a] * n;
        #pragma unroll
        for (int b = 0; b < 4; b++) {
            unsigned long long wab2 = pack2(wx[a] * wy[b]);
            const uint2* base = lat + ((size_t)(xb + Y[b]) * n) * 8 + 2 * tq;
            __half2 sA0 = zero, sA1 = zero, sB0 = zero, sB1 = zero;
            #pragma unroll
            for (int c = 0; c < 4; c++) {
                uint4 h = *reinterpret_cast<const uint4*>(base + zoff[c]);
                sA0 = __hfma2(u2h(h.x), wzh[c], sA0);
                sA1 = __hfma2(u2h(h.y), wzh[c], sA1);
                sB0 = __hfma2(u2h(h.z), wzh[c], sB0);
                sB1 = __hfma2(u2h(h.w), wzh[c], sB1);
            }
            float2 a0 = __half22float2(sA0);
            float2 a1 = __half22float2(sA1);
            float2 b0 = __half22float2(sB0);
            float2 b1 = __half22float2(sB1);
            ffma2(acc[0], pack2f(a0.x, a0.y), wab2);
            ffma2(acc[1], pack2f(a1.x, a1.y), wab2);
            ffma2(acc[2], pack2f(b0.x, b0.y), wab2);
            ffma2(acc[3], pack2f(b1.x, b1.y), wab2);
        }
    }
}

__global__ void __launch_bounds__(256)
main_kernel(ulonglong2* __restrict__ out, int P) {
    int mainBlocks = (P + 63) >> 6;
    if ((int)blockIdx.x >= mainBlocks) {
        // tail: restore hist/cur = 0 for the next graph replay
        int t = (blockIdx.x - mainBlocks) * 256 + threadIdx.x;   // 0..8191
        int4 z = make_int4(0, 0, 0, 0);
        reinterpret_cast<int4*>(g_hist)[t] = z;
        reinterpret_cast<int4*>(g_cur)[t] = z;
        return;
    }

    int warp = blockIdx.x * 8 + (threadIdx.x >> 5);
    int lane = threadIdx.x & 31;
    int sub  = lane >> 2;     // point slot within warp (0..7)
    int tq   = lane & 3;      // t-pair: owns t = 2tq, 2tq+1
    int p = warp * 8 + sub;
    bool active = p < P;

    float4 s = g_sorted[min(p, P - 1)];

    unsigned long long acc[4] = {0ULL, 0ULL, 0ULL, 0ULL};
    accum_lattice_h4(g_lat0h,  8,  7.f / 31.f, s.x, s.y, s.z, tq, acc);
    accum_lattice_h4(g_lat1h, 16, 15.f / 31.f, s.x, s.y, s.z, tq, acc);
    accum_lattice_h4(g_lat2h, 32, 31.f / 31.f, s.x, s.y, s.z, tq, acc);

    if (active) {
        int orig = __float_as_int(s.w);
        ulonglong2 oA; oA.x = acc[0]; oA.y = acc[1];   // t = 2tq
        ulonglong2 oB; oB.x = acc[2]; oB.y = acc[3];   // t = 2tq+1
        out[(size_t)(2 * tq)     * P + orig] = oA;
        out[(size_t)(2 * tq + 1) * P + orig] = oB;
    }
}

// ---------------------------------------------------------------------------
extern "C" void kernel_launch(void* const* d_in, const int* in_sizes, int n_in,
                              void* d_out, int out_size) {
    // metadata order: 0:t 1:coords 2:static_0 3:coeffs_0 4:static_1 5:coeffs_1
    //                 6:static_2 7:coeffs_2
    const float* t_in   = (const float*)d_in[0];
    const float* coords = (const float*)d_in[1];
    const float* st0 = (const float*)d_in[2];
    const float* cf0 = (const float*)d_in[3];
    const float* st1 = (const float*)d_in[4];
    const float* cf1 = (const float*)d_in[5];
    const float* st2 = (const float*)d_in[6];
    const float* cf2 = (const float*)d_in[7];
    int P = in_sizes[1] / 3;
    if (P > MAXP) P = MAXP;

    k1_hist_basis<<<(P + 255) / 256, 256>>>(t_in, coords, P);                       // 1
    k2_scan<<<1, 1024>>>();                                                         // 2
    k3_scatter_pre<<<PRE_BLOCKS + (P + 255) / 256, 256>>>(st0, cf0, st1, cf1,
                                                          st2, cf2, coords, P);     // 3
    main_kernel<<<((P + 63) / 64) + ZERO_BLOCKS, 256>>>((ulonglong2*)d_out, P);     // 4 (profiled)
}

// round 10
// speedup vs baseline: 9.0610x; 1.0437x over previous
#include <cuda_runtime.h>
#include <cuda_fp16.h>

#define T_ 8
#define K_ 4
#define B_ 8
#define MAXP 262144
#define NCELL 31
#define NB (NCELL * NCELL * NCELL)   // 29791 bins
#define NBPAD 32768
#define PRE_BLOCKS 146               // 146*256 = 37376 = 512+4096+32768 voxels
#define ZERO_BLOCKS 32               // 32*256 threads x int4 = 32768 ints per array

// Per-voxel time-expanded lattices in FP16:
// slice (voxel v, t) = uint2 = { half2(k0,k1), half2(k2,k3) } -> voxel line = 64 B
__device__ uint2 g_lat0h[512 * 8];
__device__ uint2 g_lat1h[4096 * 8];
__device__ uint2 g_lat2h[32768 * 8];
__device__ float g_basis[T_ * B_];

// Counting sort (padded to 32768 for vector scan; extras stay zero)
__device__ float4 g_sorted[MAXP];
__device__ __align__(16) int g_hist[NBPAD];   // zero-init at load; re-zeroed each call by main tail
__device__ __align__(16) int g_base[NBPAD];
__device__ __align__(16) int g_cur[NBPAD];

__constant__ float c_knots[12] = {0.f,0.f,0.f,0.f,1.f,2.f,4.f,8.f,16.f,16.f,16.f,16.f};

// ---------------------------------------------------------------------------
__device__ __forceinline__ int cell_of(float px, float py, float pz) {
    int fx = min(max((int)floorf(px), 0), NCELL - 1);
    int fy = min(max((int)floorf(py), 0), NCELL - 1);
    int fz = min(max((int)floorf(pz), 0), NCELL - 1);
    return (fx * NCELL + fy) * NCELL + fz;
}

// ---------------------------------------------------------------------------
// Launch 1: histogram + Cox-de Boor basis (block 0, threads 0-7)
// ---------------------------------------------------------------------------
__global__ void k1_hist_basis(const float* __restrict__ t_in,
                              const float* __restrict__ coords, int P) {
    int p = blockIdx.x * blockDim.x + threadIdx.x;
    if (p < P)
        atomicAdd(&g_hist[cell_of(coords[3*p], coords[3*p+1], coords[3*p+2])], 1);

    if (blockIdx.x == 0 && threadIdx.x < T_) {
        int ti = threadIdx.x;
        float t = t_in[ti];
        float N[11];
        #pragma unroll
        for (int i = 0; i < 11; i++) {
            float l = c_knots[i], r = c_knots[i + 1];
            bool m = (i < 10) ? (t >= l && t < r) : (t >= l && t <= r);
            N[i] = m ? 1.f : 0.f;
        }
        #pragma unroll
        for (int q = 1; q <= 3; q++) {
            float Nn[11];
            for (int i = 0; i < 11 - q; i++) {
                float l = c_knots[i], mid = c_knots[i + q];
                float rr = c_knots[i + 1], fr = c_knots[i + q + 1];
                float term = 0.f;
                if (mid > l)  term += (t - l) / (mid - l) * N[i];
                if (fr > rr)  term += (fr - t) / (fr - rr) * N[i + 1];
                Nn[i] = term;
            }
            for (int i = 0; i < 11 - q; i++) N[i] = Nn[i];
        }
        #pragma unroll
        for (int b = 0; b < B_; b++) g_basis[ti * B_ + b] = N[b];
    }
}

// ---------------------------------------------------------------------------
// Launch 2: vectorized exclusive scan of g_hist -> g_base (32768 entries)
// ---------------------------------------------------------------------------
__global__ void k2_scan() {
    __shared__ int wsum[32];
    int tid = threadIdx.x, lane = tid & 31, wid = tid >> 5;
    int4 v[8]; int s = 0;
    const int4* hp = reinterpret_cast<const int4*>(g_hist) + tid * 8;
    #pragma unroll
    for (int j = 0; j < 8; j++) { v[j] = hp[j]; s += v[j].x + v[j].y + v[j].z + v[j].w; }
    int incl = s;
    #pragma unroll
    for (int o = 1; o < 32; o <<= 1) { int t = __shfl_up_sync(~0u, incl, o); if (lane >= o) incl += t; }
    if (lane == 31) wsum[wid] = incl;
    __syncthreads();
    if (wid == 0) {
        int w = wsum[lane];
        int wi = w;
        #pragma unroll
        for (int o = 1; o < 32; o <<= 1) { int t = __shfl_up_sync(~0u, wi, o); if (lane >= o) wi += t; }
        wsum[lane] = wi - w;   // exclusive across warps
    }
    __syncthreads();
    int run = wsum[wid] + (incl - s);
    int4* bp = reinterpret_cast<int4*>(g_base) + tid * 8;
    #pragma unroll
    for (int j = 0; j < 8; j++) {
        int4 o;
        o.x = run; run += v[j].x;
        o.y = run; run += v[j].y;
        o.z = run; run += v[j].z;
        o.w = run; run += v[j].w;
        bp[j] = o;
    }
}

// ---------------------------------------------------------------------------
// Launch 3: fused scatter + lattice precompute
// ---------------------------------------------------------------------------
__device__ __forceinline__ unsigned h2u(__half2 h) { return *reinterpret_cast<unsigned*>(&h); }
__device__ __forceinline__ __half2 u2h(unsigned u) { __half2 h; *reinterpret_cast<unsigned*>(&h) = u; return h; }

__device__ __forceinline__ void pre_one(const float* __restrict__ stat,
                                        const float* __restrict__ coef,
                                        uint2* __restrict__ lat, int Nvox, int v) {
    float bas[T_ * B_];
    #pragma unroll
    for (int i = 0; i < T_ * B_; i++) bas[i] = g_basis[i];

    float st[K_];
    #pragma unroll
    for (int k = 0; k < K_; k++) st[k] = stat[k * Nvox + v];

    float cf[K_][B_];
    #pragma unroll
    for (int k = 0; k < K_; k++) {
        const float4* cp = reinterpret_cast<const float4*>(coef + ((size_t)(k * Nvox) + v) * B_);
        float4 c0 = cp[0], c1 = cp[1];
        cf[k][0] = c0.x; cf[k][1] = c0.y; cf[k][2] = c0.z; cf[k][3] = c0.w;
        cf[k][4] = c1.x; cf[k][5] = c1.y; cf[k][6] = c1.z; cf[k][7] = c1.w;
    }
    #pragma unroll
    for (int t = 0; t < T_; t++) {
        float o[K_];
        #pragma unroll
        for (int k = 0; k < K_; k++) {
            float s = st[k];
            #pragma unroll
            for (int b = 0; b < B_; b++) s = fmaf(bas[t * B_ + b], cf[k][b], s);
            o[k] = s;
        }
        uint2 r;
        r.x = h2u(__floats2half2_rn(o[0], o[1]));
        r.y = h2u(__floats2half2_rn(o[2], o[3]));
        lat[(size_t)v * 8 + t] = r;
    }
}

__global__ void k3_scatter_pre(const float* __restrict__ st0, const float* __restrict__ cf0,
                               const float* __restrict__ st1, const float* __restrict__ cf1,
                               const float* __restrict__ st2, const float* __restrict__ cf2,
                               const float* __restrict__ coords, int P) {
    if (blockIdx.x < PRE_BLOCKS) {
        int v = blockIdx.x * 256 + threadIdx.x;
        if (v < 512)       pre_one(st0, cf0, g_lat0h, 512,   v);
        else if (v < 4608) pre_one(st1, cf1, g_lat1h, 4096,  v - 512);
        else               pre_one(st2, cf2, g_lat2h, 32768, v - 4608);
    } else {
        int p = (blockIdx.x - PRE_BLOCKS) * 256 + threadIdx.x;
        if (p >= P) return;
        float px = coords[3*p], py = coords[3*p+1], pz = coords[3*p+2];
        int bin = cell_of(px, py, pz);
        int pos = g_base[bin] + atomicAdd(&g_cur[bin], 1);
        g_sorted[pos] = make_float4(px, py, pz, __int_as_float(p));
    }
}

// ---------------------------------------------------------------------------
// Launch 4 (PROFILED): cooperative tricubic gather, fp16 taps.
// 4 lanes per point, 8 sorted points/warp. Templated N -> shift addressing;
// warp-uniform interior fast path: all 64 taps at [base + compile-time imm].
// ---------------------------------------------------------------------------
__device__ __forceinline__ void cubw(float u, float w[4]) {
    float u2 = u * u, u3 = u2 * u;
    w[0] = (1.f / 6.f) * (1.f - 3.f * u + 3.f * u2 - u3);
    w[1] = (1.f / 6.f) * (4.f - 6.f * u2 + 3.f * u3);
    w[2] = (1.f / 6.f) * (1.f + 3.f * u + 3.f * u2 - 3.f * u3);
    w[3] = (1.f / 6.f) * u3;
}

__device__ __forceinline__ unsigned long long pack2(float w) {
    unsigned long long r;
    unsigned int wi = __float_as_uint(w);
    asm("mov.b64 %0, {%1, %1};" : "=l"(r) : "r"(wi));
    return r;
}

__device__ __forceinline__ unsigned long long pack2f(float a, float b) {
    unsigned long long r;
    asm("mov.b64 %0, {%1, %2};" : "=l"(r) : "f"(a), "f"(b));
    return r;
}

__device__ __forceinline__ void ffma2(unsigned long long& d,
                                      unsigned long long a,
                                      unsigned long long b) {
    asm("fma.rn.f32x2 %0, %1, %2, %0;" : "+l"(d) : "l"(a), "l"(b));
}

// one (a,b) row: 4 z-taps from 4 source slices + fold into fp32x2 accumulators
__device__ __forceinline__ void row_accum(const uint4 h[4], const __half2 wzh[4],
                                          float wab, unsigned long long acc[4]) {
    const __half2 zero = __floats2half2_rn(0.f, 0.f);
    __half2 sA0 = zero, sA1 = zero, sB0 = zero, sB1 = zero;
    #pragma unroll
    for (int c = 0; c < 4; c++) {
        sA0 = __hfma2(u2h(h[c].x), wzh[c], sA0);
        sA1 = __hfma2(u2h(h[c].y), wzh[c], sA1);
        sB0 = __hfma2(u2h(h[c].z), wzh[c], sB0);
        sB1 = __hfma2(u2h(h[c].w), wzh[c], sB1);
    }
    unsigned long long wab2 = pack2(wab);
    float2 a0 = __half22float2(sA0);
    float2 a1 = __half22float2(sA1);
    float2 b0 = __half22float2(sB0);
    float2 b1 = __half22float2(sB1);
    ffma2(acc[0], pack2f(a0.x, a0.y), wab2);
    ffma2(acc[1], pack2f(a1.x, a1.y), wab2);
    ffma2(acc[2], pack2f(b0.x, b0.y), wab2);
    ffma2(acc[3], pack2f(b1.x, b1.y), wab2);
}

template<int N>
__device__ __forceinline__ void accum_lattice_h4(const uint2* __restrict__ lat,
                                                 float scale, float px, float py, float pz,
                                                 int tq, unsigned long long acc[4]) {
    float cx = px * scale, cy = py * scale, cz = pz * scale;
    float fx = floorf(cx), fy = floorf(cy), fz = floorf(cz);
    int ix = (int)fx - 1, iy = (int)fy - 1, iz = (int)fz - 1;
    float wx[4], wy[4], wz[4];
    cubw(cx - fx, wx); cubw(cy - fy, wy); cubw(cz - fz, wz);
    __half2 wzh[4];
    #pragma unroll
    for (int a = 0; a < 4; a++) wzh[a] = __floats2half2_rn(wz[a], wz[a]);

    bool interior = (ix >= 0) & (iy >= 0) & (iz >= 0) &
                    (ix + 3 < N) & (iy + 3 < N) & (iz + 3 < N);

    if (__all_sync(~0u, interior)) {
        // all 64 taps at [base + compile-time immediate]
        const uint2* base = lat + ((ix * N + iy) * N + iz) * 8 + 2 * tq;
        #pragma unroll
        for (int a = 0; a < 4; a++) {
            #pragma unroll
            for (int b = 0; b < 4; b++) {
                uint4 h[4];
                #pragma unroll
                for (int c = 0; c < 4; c++)
                    h[c] = *reinterpret_cast<const uint4*>(base + ((a * N + b) * N + c) * 8);
                row_accum(h, wzh, wx[a] * wy[b], acc);
            }
        }
    } else {
        int X[4], Y[4], zoff[4];
        #pragma unroll
        for (int a = 0; a < 4; a++) {
            X[a] = min(max(ix + a, 0), N - 1);
            Y[a] = min(max(iy + a, 0), N - 1);
            zoff[a] = min(max(iz + a, 0), N - 1) * 8;
        }
        #pragma unroll
        for (int a = 0; a < 4; a++) {
            int xb = X[a] * N;
            #pragma unroll
            for (int b = 0; b < 4; b++) {
                const uint2* base = lat + (xb + Y[b]) * N * 8 + 2 * tq;
                uint4 h[4];
                #pragma unroll
                for (int c = 0; c < 4; c++)
                    h[c] = *reinterpret_cast<const uint4*>(base + zoff[c]);
                row_accum(h, wzh, wx[a] * wy[b], acc);
            }
        }
    }
}

__global__ void __launch_bounds__(256, 4)
main_kernel(ulonglong2* __restrict__ out, int P) {
    int mainBlocks = (P + 63) >> 6;
    if ((int)blockIdx.x >= mainBlocks) {
        // tail: restore hist/cur = 0 for the next graph replay
        int t = (blockIdx.x - mainBlocks) * 256 + threadIdx.x;   // 0..8191
        int4 z = make_int4(0, 0, 0, 0);
        reinterpret_cast<int4*>(g_hist)[t] = z;
        reinterpret_cast<int4*>(g_cur)[t] = z;
        return;
    }

    int warp = blockIdx.x * 8 + (threadIdx.x >> 5);
    int lane = threadIdx.x & 31;
    int sub  = lane >> 2;     // point slot within warp (0..7)
    int tq   = lane & 3;      // t-pair: owns t = 2tq, 2tq+1
    int p = warp * 8 + sub;
    bool active = p < P;

    float4 s = g_sorted[min(p, P - 1)];

    unsigned long long acc[4] = {0ULL, 0ULL, 0ULL, 0ULL};
    accum_lattice_h4<8 >(g_lat0h,  7.f / 31.f, s.x, s.y, s.z, tq, acc);
    accum_lattice_h4<16>(g_lat1h, 15.f / 31.f, s.x, s.y, s.z, tq, acc);
    accum_lattice_h4<32>(g_lat2h, 31.f / 31.f, s.x, s.y, s.z, tq, acc);

    if (active) {
        int orig = __float_as_int(s.w);
        ulonglong2 oA; oA.x = acc[0]; oA.y = acc[1];   // t = 2tq
        ulonglong2 oB; oB.x = acc[2]; oB.y = acc[3];   // t = 2tq+1
        out[(size_t)(2 * tq)     * P + orig] = oA;
        out[(size_t)(2 * tq + 1) * P + orig] = oB;
    }
}

// ---------------------------------------------------------------------------
extern "C" void kernel_launch(void* const* d_in, const int* in_sizes, int n_in,
                              void* d_out, int out_size) {
    // metadata order: 0:t 1:coords 2:static_0 3:coeffs_0 4:static_1 5:coeffs_1
    //                 6:static_2 7:coeffs_2
    const float* t_in   = (const float*)d_in[0];
    const float* coords = (const float*)d_in[1];
    const float* st0 = (const float*)d_in[2];
    const float* cf0 = (const float*)d_in[3];
    const float* st1 = (const float*)d_in[4];
    const float* cf1 = (const float*)d_in[5];
    const float* st2 = (const float*)d_in[6];
    const float* cf2 = (const float*)d_in[7];
    int P = in_sizes[1] / 3;
    if (P > MAXP) P = MAXP;

    k1_hist_basis<<<(P + 255) / 256, 256>>>(t_in, coords, P);                       // 1
    k2_scan<<<1, 1024>>>();                                                         // 2
    k3_scatter_pre<<<PRE_BLOCKS + (P + 255) / 256, 256>>>(st0, cf0, st1, cf1,
                                                          st2, cf2, coords, P);     // 3
    main_kernel<<<((P + 63) / 64) + ZERO_BLOCKS, 256>>>((ulonglong2*)d_out, P);     // 4 (profiled)
}